// round 4
// baseline (speedup 1.0000x reference)
#include <cuda_runtime.h>
#include <math.h>
#include <stdint.h>

#define B 16
#define T 2048
#define D 512
#define C 512
#define KW 11
#define KHALF 5
#define THRESH 0.9f
#define MAXTOK 128
#define TILE 32   // t-tile per k_logit block
#define CH 64     // timestep chunk per k_fired block

// ---------------- scratch (no allocation allowed) ----------------
__device__ __align__(16) float g_weff[KW * D];
__device__ float g_beff;
__device__ float g_logit[B * T];
__device__ float g_anorm[B * T];       // alpha_norm
__device__ int   g_fire_t[B * MAXTOK]; // fire time of token n
__device__ float g_fak1[B * MAXTOK];   // ak1 at fire n
__device__ float g_fak2[B * MAXTOK];   // ak2 at fire n
__device__ int   g_nf[B];              // number of fired tokens per batch

// ---- packed f32x2 helpers (sm_103a) ----
__device__ __forceinline__ unsigned long long pack2(float a, float b) {
    unsigned long long r;
    asm("mov.b64 %0, {%1, %2};" : "=l"(r) : "f"(a), "f"(b));
    return r;
}
__device__ __forceinline__ void unpack2(unsigned long long v, float& a, float& b) {
    asm("mov.b64 {%0, %1}, %2;" : "=f"(a), "=f"(b) : "l"(v));
}
#define FMA2(accv, av, bv) \
    asm("fma.rn.f32x2 %0, %1, %2, %0;" : "+l"(accv) : "l"(av), "l"(bv))

// ---------------- kernel 1: fold projection into conv weights ----------------
__global__ void k_weff(const float* __restrict__ conv_w,
                       const float* __restrict__ conv_b,
                       const float* __restrict__ proj_w,
                       const float* __restrict__ proj_b) {
    int wid  = blockIdx.x * (blockDim.x >> 5) + (threadIdx.x >> 5);
    int lane = threadIdx.x & 31;
    if (wid < KW * D) {
        const float* row = conv_w + (size_t)wid * C;
        float s = 0.f;
        #pragma unroll 4
        for (int c = lane; c < C; c += 32) s += row[c] * proj_w[c];
        #pragma unroll
        for (int o = 16; o; o >>= 1) s += __shfl_down_sync(0xffffffffu, s, o);
        if (lane == 0) g_weff[wid] = s;
    } else if (wid == KW * D) {
        float s = 0.f;
        for (int c = lane; c < C; c += 32) s += conv_b[c] * proj_w[c];
        #pragma unroll
        for (int o = 16; o; o >>= 1) s += __shfl_down_sync(0xffffffffu, s, o);
        if (lane == 0) g_beff = s + proj_b[0];
    }
}

// ---------------- kernel 2: direct conv logits, register sliding window ------
// grid (T/TILE, B), 256 threads: thread owns float2 d-slice; weights + TILE
// f32x2 accumulators in registers; each eouts element loaded exactly once.
__global__ void __launch_bounds__(256, 4)
k_logit(const float* __restrict__ eouts) {
    int b = blockIdx.y;
    int t0 = blockIdx.x * TILE;
    int tid = threadIdx.x;  // 0..255

    unsigned long long w[KW];
    #pragma unroll
    for (int k = 0; k < KW; k++) {
        float2 wv = ((const float2*)(g_weff + k * D))[tid];
        w[k] = pack2(wv.x, wv.y);
    }

    unsigned long long acc[TILE];
    unsigned long long z = pack2(0.f, 0.f);
    #pragma unroll
    for (int i = 0; i < TILE; i++) acc[i] = z;

    const float2* eb = (const float2*)(eouts + (size_t)b * T * D);
    #pragma unroll
    for (int tt = 0; tt < TILE + 2 * KHALF; tt++) {
        int t = t0 + tt - KHALF;
        float2 v = make_float2(0.f, 0.f);
        if (t >= 0 && t < T) v = eb[(size_t)t * (D / 2) + tid];
        unsigned long long vp = pack2(v.x, v.y);
        #pragma unroll
        for (int k = 0; k < KW; k++) {
            int i = tt - k;             // compile-time constant per (tt,k)
            if (i >= 0 && i < TILE) FMA2(acc[i], vp, w[k]);
        }
    }

    // reduce 256 d-slices per output
    __shared__ float s[TILE][257];
    #pragma unroll
    for (int i = 0; i < TILE; i++) {
        float lo, hi;
        unpack2(acc[i], lo, hi);
        s[i][tid] = lo + hi;
    }
    __syncthreads();
    __shared__ float s2[TILE][8];
    {
        int i = tid >> 3, seg = tid & 7;   // 32 outputs x 8 segments
        float sum = 0.f;
        #pragma unroll
        for (int j = 0; j < 32; j++) sum += s[i][seg * 32 + j];
        s2[i][seg] = sum;
    }
    __syncthreads();
    if (tid < TILE) {
        float tot = g_beff;
        #pragma unroll
        for (int j = 0; j < 8; j++) tot += s2[tid][j];
        g_logit[b * T + t0 + tid] = tot;
    }
}

// ---------------- kernel 3: alpha + prefix + ballot fire search --------------
// one block of 1024 threads per batch
__global__ void k_alpha_scan(float* __restrict__ out_alpha,
                             float* __restrict__ aws,
                             const int* __restrict__ elens,
                             const int* __restrict__ ylens, int L) {
    int b = blockIdx.x;
    int tid = threadIdx.x;
    int lane = tid & 31, wid = tid >> 5;

    __shared__ float  sA[T];        // alpha_norm
    __shared__ double sS[T];        // inclusive prefix of alpha_norm
    __shared__ double sWarp[32];
    __shared__ int    s_fire_t[MAXTOK];
    __shared__ float  s_ak1[MAXTOK], s_ak2[MAXTOK];
    __shared__ int    s_ntok;
    __shared__ float  s_asum;

    int el = elens[b];
    int yl = ylens[b];

    // --- step 1: sigmoid alphas + block reduce for asum ---
    float a0, a1;
    {
        double local = 0.0;
        #pragma unroll
        for (int rep = 0; rep < 2; rep++) {
            int t = tid + rep * 1024;
            float lg = g_logit[b * T + t];
            float a = 1.f / (1.f + expf(-lg));
            if (rep == 0) a0 = a; else a1 = a;
            local += (double)a;
        }
        #pragma unroll
        for (int o = 16; o; o >>= 1) local += __shfl_down_sync(0xffffffffu, local, o);
        if (lane == 0) sWarp[wid] = local;
        __syncthreads();
        if (wid == 0) {
            double v = sWarp[lane];
            #pragma unroll
            for (int o = 16; o; o >>= 1) v += __shfl_down_sync(0xffffffffu, v, o);
            if (lane == 0) s_asum = (float)v;
        }
        __syncthreads();
    }
    float asum = s_asum;
    float ylf = (float)yl;

    // --- step 2: alpha_norm ---
    {
        int t0 = tid, t1 = tid + 1024;
        float an0 = a0 / asum * ylf;
        float an1 = a1 / asum * ylf;
        sA[t0] = an0; sA[t1] = an1;
        out_alpha[b * T + t0] = a0;  out_alpha[b * T + t1] = a1;
        g_anorm[b * T + t0] = an0;   g_anorm[b * T + t1] = an1;
    }
    __syncthreads();

    // --- step 3: block inclusive prefix scan (double) ---
    {
        float e0 = sA[2 * tid], e1 = sA[2 * tid + 1];
        double my = (double)e0 + (double)e1;
        double v = my;
        #pragma unroll
        for (int o = 1; o < 32; o <<= 1) {
            double n = __shfl_up_sync(0xffffffffu, v, o);
            if (lane >= o) v += n;
        }
        if (lane == 31) sWarp[wid] = v;
        __syncthreads();
        if (wid == 0) {
            double w = sWarp[lane];
            #pragma unroll
            for (int o = 1; o < 32; o <<= 1) {
                double n = __shfl_up_sync(0xffffffffu, w, o);
                if (lane >= o) w += n;
            }
            sWarp[lane] = w;
        }
        __syncthreads();
        double base = (wid ? sWarp[wid - 1] : 0.0) + (v - my);
        sS[2 * tid]     = base + (double)e0;
        sS[2 * tid + 1] = base + (double)e0 + (double)e1;
    }
    __syncthreads();

    // --- step 4: warp 0 finds fires via monotone ballot sweep ---
    if (wid == 0) {
        double Ccorr = 0.0;
        int ntok = 0;
        int pos = 0;
        while (ntok < yl) {
            double th = (double)THRESH - Ccorr;
            int found = -1;
            for (int base = pos; base < el; base += 32) {
                int t = base + lane;
                bool hit = (t < el) && (sS[t] >= th);
                unsigned m = __ballot_sync(0xffffffffu, hit);
                if (m) { found = base + __ffs(m) - 1; break; }
            }
            if (found < 0) break;
            float a = sA[found];
            float acc = (float)(sS[found] + Ccorr);
            float ak1 = 1.f - acc;
            float ak2 = a - ak1;
            if (lane == 0) {
                s_fire_t[ntok] = found;
                s_ak1[ntok] = ak1;
                s_ak2[ntok] = ak2;
            }
            Ccorr += (double)a - 1.0;
            ntok++;
            pos = found + 1;
        }
        __syncwarp();
        if (lane == 0) { s_ntok = ntok; g_nf[b] = ntok; }
        for (int i = lane; i < ntok; i += 32) {
            g_fire_t[b * MAXTOK + i] = s_fire_t[i];
            g_fak1[b * MAXTOK + i] = s_ak1[i];
            g_fak2[b * MAXTOK + i] = s_ak2[i];
        }
    }
    __syncthreads();

    // --- step 5: fill aws sparse entries (memset provided the zeros) ---
    int ntok = s_ntok;
    float* awb = aws + (size_t)b * (L + 1) * T;
    for (int t = tid; t < el; t += 1024) {
        int lo = 0, hi = ntok;
        while (lo < hi) {
            int m = (lo + hi) >> 1;
            if (s_fire_t[m] < t) lo = m + 1; else hi = m;
        }
        int row = lo;
        if (row < ntok && s_fire_t[row] == t) {
            awb[row * T + t] = s_ak1[row];
            awb[(row + 1) * T + t] = s_ak2[row];
        } else if (row < yl) {
            awb[row * T + t] = sA[t];
        }
    }
}

// ---------------- kernel 4: uniform time-chunked reduction -> fired ----------
// grid (T/CH, B), 128 threads; every block does exactly CH coalesced float4
// loads per thread with a branch-uniform weight schedule; token boundaries
// flush the running accumulator via atomicAdd (fired pre-zeroed by memset).
__global__ void __launch_bounds__(128)
k_fired(const float* __restrict__ eouts, float* __restrict__ fired, int L) {
    int b = blockIdx.y;
    int c0 = blockIdx.x * CH;
    int tid = threadIdx.x;  // 0..127

    __shared__ float sW1[CH], sW2[CH];
    __shared__ int   sFire[CH];
    __shared__ int   sRow0;

    int nf = g_nf[b];

    if (tid < CH) {
        int t = c0 + tid;
        const int* ft = g_fire_t + b * MAXTOK;
        int lo = 0, hi = nf;
        while (lo < hi) {
            int m = (lo + hi) >> 1;
            if (ft[m] < t) lo = m + 1; else hi = m;
        }
        int rw = lo;   // # fires strictly before t
        float w1 = 0.f, w2 = 0.f;
        int fi = 0;
        if (rw < nf) {
            if (ft[rw] == t) {
                fi = 1;
                w1 = g_fak1[b * MAXTOK + rw];
                w2 = g_fak2[b * MAXTOK + rw];
            } else {
                w1 = g_anorm[b * T + t];
            }
        }
        sW1[tid] = w1; sW2[tid] = w2; sFire[tid] = fi;
        if (tid == 0) sRow0 = rw;
    }
    __syncthreads();

    int cur = sRow0;
    const float4* eb = (const float4*)(eouts + (size_t)b * T * D);
    float* fb = fired + (size_t)b * L * D;
    float4 acc = make_float4(0.f, 0.f, 0.f, 0.f);

    #pragma unroll 4
    for (int tt = 0; tt < CH; tt++) {
        float4 v = eb[(size_t)(c0 + tt) * 128 + tid];
        float w1 = sW1[tt];
        acc.x += w1 * v.x; acc.y += w1 * v.y;
        acc.z += w1 * v.z; acc.w += w1 * v.w;
        if (sFire[tt]) {                   // uniform across the block
            float* dst = fb + (size_t)cur * D + tid * 4;
            atomicAdd(dst + 0, acc.x); atomicAdd(dst + 1, acc.y);
            atomicAdd(dst + 2, acc.z); atomicAdd(dst + 3, acc.w);
            float w2 = sW2[tt];
            acc.x = w2 * v.x; acc.y = w2 * v.y;
            acc.z = w2 * v.z; acc.w = w2 * v.w;
            cur++;
        }
    }
    if (cur < nf) {                        // partial segment continues next chunk
        float* dst = fb + (size_t)cur * D + tid * 4;
        atomicAdd(dst + 0, acc.x); atomicAdd(dst + 1, acc.y);
        atomicAdd(dst + 2, acc.z); atomicAdd(dst + 3, acc.w);
    }
}

// ---------------- launch ------------------------------------------------------
extern "C" void kernel_launch(void* const* d_in, const int* in_sizes, int n_in,
                              void* d_out, int out_size) {
    const float* eouts  = (const float*)d_in[0];
    const float* conv_w = (const float*)d_in[1];
    const float* conv_b = (const float*)d_in[2];
    const float* proj_w = (const float*)d_in[3];
    const float* proj_b = (const float*)d_in[4];
    const int*   elens  = (const int*)d_in[5];
    const int*   ylens  = (const int*)d_in[6];

    // out = concat(fired[B,L,D], alpha[B,T], aws[B,1,L+1,T])
    int L = (out_size - 2 * B * T) / (B * D + B * T);

    float* out   = (float*)d_out;
    float* fired = out;
    float* alpha = out + (size_t)B * L * D;
    float* aws   = alpha + (size_t)B * T;

    cudaMemsetAsync(d_out, 0, (size_t)out_size * sizeof(float));

    k_weff<<<(KW * D + 1 + 7) / 8, 256>>>(conv_w, conv_b, proj_w, proj_b);
    k_logit<<<dim3(T / TILE, B), 256>>>(eouts);
    k_alpha_scan<<<B, 1024>>>(alpha, aws, elens, ylens, L);
    k_fired<<<dim3(T / CH, B), 128>>>(eouts, fired, L);
}

// round 5
// speedup vs baseline: 1.5370x; 1.5370x over previous
#include <cuda_runtime.h>
#include <math.h>
#include <stdint.h>

#define B 16
#define T 2048
#define D 512
#define C 512
#define KW 11
#define KHALF 5
#define THRESH 0.9f
#define MAXTOK 128
#define TILE 32   // t-tile per k_logit block

// ---------------- scratch (no allocation allowed) ----------------
__device__ __align__(16) float g_weff[KW * D];
__device__ float g_beff;
__device__ float g_logit[B * T];
__device__ float g_anorm[B * T];       // alpha_norm
__device__ int   g_fire_t[B * MAXTOK]; // fire time of token n
__device__ float g_fak1[B * MAXTOK];   // ak1 at fire n
__device__ float g_fak2[B * MAXTOK];   // ak2 at fire n
__device__ int   g_nf[B];              // number of fired tokens per batch

// ---- packed f32x2 helpers (sm_103a) ----
__device__ __forceinline__ unsigned long long pack2(float a, float b) {
    unsigned long long r;
    asm("mov.b64 %0, {%1, %2};" : "=l"(r) : "f"(a), "f"(b));
    return r;
}
__device__ __forceinline__ void unpack2(unsigned long long v, float& a, float& b) {
    asm("mov.b64 {%0, %1}, %2;" : "=f"(a), "=f"(b) : "l"(v));
}
#define FMA2(accv, av, bv) \
    asm("fma.rn.f32x2 %0, %1, %2, %0;" : "+l"(accv) : "l"(av), "l"(bv))

// ---------------- kernel 1: fold projection into conv weights ----------------
__global__ void k_weff(const float* __restrict__ conv_w,
                       const float* __restrict__ conv_b,
                       const float* __restrict__ proj_w,
                       const float* __restrict__ proj_b) {
    int wid  = blockIdx.x * (blockDim.x >> 5) + (threadIdx.x >> 5);
    int lane = threadIdx.x & 31;
    if (wid < KW * D) {
        const float* row = conv_w + (size_t)wid * C;
        float s = 0.f;
        #pragma unroll 4
        for (int c = lane; c < C; c += 32) s += row[c] * proj_w[c];
        #pragma unroll
        for (int o = 16; o; o >>= 1) s += __shfl_down_sync(0xffffffffu, s, o);
        if (lane == 0) g_weff[wid] = s;
    } else if (wid == KW * D) {
        float s = 0.f;
        for (int c = lane; c < C; c += 32) s += conv_b[c] * proj_w[c];
        #pragma unroll
        for (int o = 16; o; o >>= 1) s += __shfl_down_sync(0xffffffffu, s, o);
        if (lane == 0) g_beff = s + proj_b[0];
    }
}

// ---------------- kernel 2: direct conv logits, register sliding window ------
// grid (T/TILE, B), 128 threads: thread owns float4 d-slice, weights + 32
// f32x2-pair accumulators in registers, each eouts element loaded exactly once.
__global__ void __launch_bounds__(128, 3)
k_logit(const float* __restrict__ eouts) {
    int b = blockIdx.y;
    int t0 = blockIdx.x * TILE;
    int tid = threadIdx.x;  // 0..127

    unsigned long long w01[KW], w23[KW];
    #pragma unroll
    for (int k = 0; k < KW; k++) {
        float4 w = ((const float4*)(g_weff + k * D))[tid];
        w01[k] = pack2(w.x, w.y);
        w23[k] = pack2(w.z, w.w);
    }

    unsigned long long acc[TILE];
    unsigned long long z = pack2(0.f, 0.f);
    #pragma unroll
    for (int i = 0; i < TILE; i++) acc[i] = z;

    const float4* eb = (const float4*)(eouts + (size_t)b * T * D);
    #pragma unroll
    for (int tt = 0; tt < TILE + 2 * KHALF; tt++) {
        int t = t0 + tt - KHALF;
        float4 v = make_float4(0.f, 0.f, 0.f, 0.f);
        if (t >= 0 && t < T) v = eb[(size_t)t * (D / 4) + tid];
        unsigned long long v01 = pack2(v.x, v.y);
        unsigned long long v23 = pack2(v.z, v.w);
        #pragma unroll
        for (int k = 0; k < KW; k++) {
            int i = tt - k;             // compile-time constant per (tt,k)
            if (i >= 0 && i < TILE) {
                FMA2(acc[i], v01, w01[k]);
                FMA2(acc[i], v23, w23[k]);
            }
        }
    }

    // reduce 128 d-slices per output
    __shared__ float s[TILE][129];
    #pragma unroll
    for (int i = 0; i < TILE; i++) {
        float lo, hi;
        unpack2(acc[i], lo, hi);
        s[i][tid] = lo + hi;
    }
    __syncthreads();
    __shared__ float s2[TILE][4];
    {
        int i = tid >> 2, seg = tid & 3;
        float sum = 0.f;
        #pragma unroll
        for (int j = 0; j < 32; j++) sum += s[i][seg * 32 + j];
        s2[i][seg] = sum;
    }
    __syncthreads();
    if (tid < TILE) {
        float tot = s2[tid][0] + s2[tid][1] + s2[tid][2] + s2[tid][3] + g_beff;
        g_logit[b * T + t0 + tid] = tot;
    }
}

// ---------------- kernel 3: alpha + prefix + ballot fire search --------------
// one block of 1024 threads per batch
__global__ void k_alpha_scan(float* __restrict__ out_alpha,
                             float* __restrict__ aws,
                             const int* __restrict__ elens,
                             const int* __restrict__ ylens, int L) {
    int b = blockIdx.x;
    int tid = threadIdx.x;
    int lane = tid & 31, wid = tid >> 5;

    __shared__ float  sA[T];        // alpha_norm
    __shared__ double sS[T];        // inclusive prefix of alpha_norm
    __shared__ double sWarp[32];
    __shared__ int    s_fire_t[MAXTOK];
    __shared__ float  s_ak1[MAXTOK], s_ak2[MAXTOK];
    __shared__ int    s_ntok;
    __shared__ float  s_asum;

    int el = elens[b];
    int yl = ylens[b];

    // --- step 1: sigmoid alphas + block reduce for asum ---
    float a0, a1;
    {
        double local = 0.0;
        #pragma unroll
        for (int rep = 0; rep < 2; rep++) {
            int t = tid + rep * 1024;
            float lg = g_logit[b * T + t];
            float a = 1.f / (1.f + expf(-lg));
            if (rep == 0) a0 = a; else a1 = a;
            local += (double)a;
        }
        #pragma unroll
        for (int o = 16; o; o >>= 1) local += __shfl_down_sync(0xffffffffu, local, o);
        if (lane == 0) sWarp[wid] = local;
        __syncthreads();
        if (wid == 0) {
            double v = sWarp[lane];
            #pragma unroll
            for (int o = 16; o; o >>= 1) v += __shfl_down_sync(0xffffffffu, v, o);
            if (lane == 0) s_asum = (float)v;
        }
        __syncthreads();
    }
    float asum = s_asum;
    float ylf = (float)yl;

    // --- step 2: alpha_norm ---
    {
        int t0 = tid, t1 = tid + 1024;
        float an0 = a0 / asum * ylf;
        float an1 = a1 / asum * ylf;
        sA[t0] = an0; sA[t1] = an1;
        out_alpha[b * T + t0] = a0;  out_alpha[b * T + t1] = a1;
        g_anorm[b * T + t0] = an0;   g_anorm[b * T + t1] = an1;
    }
    __syncthreads();

    // --- step 3: block inclusive prefix scan (double) ---
    {
        float e0 = sA[2 * tid], e1 = sA[2 * tid + 1];
        double my = (double)e0 + (double)e1;
        double v = my;
        #pragma unroll
        for (int o = 1; o < 32; o <<= 1) {
            double n = __shfl_up_sync(0xffffffffu, v, o);
            if (lane >= o) v += n;
        }
        if (lane == 31) sWarp[wid] = v;
        __syncthreads();
        if (wid == 0) {
            double w = sWarp[lane];
            #pragma unroll
            for (int o = 1; o < 32; o <<= 1) {
                double n = __shfl_up_sync(0xffffffffu, w, o);
                if (lane >= o) w += n;
            }
            sWarp[lane] = w;
        }
        __syncthreads();
        double base = (wid ? sWarp[wid - 1] : 0.0) + (v - my);
        sS[2 * tid]     = base + (double)e0;
        sS[2 * tid + 1] = base + (double)e0 + (double)e1;
    }
    __syncthreads();

    // --- step 4: warp 0 finds fires via monotone ballot sweep ---
    if (wid == 0) {
        double Ccorr = 0.0;
        int ntok = 0;
        int pos = 0;
        while (ntok < yl) {
            double th = (double)THRESH - Ccorr;
            int found = -1;
            for (int base = pos; base < el; base += 32) {
                int t = base + lane;
                bool hit = (t < el) && (sS[t] >= th);
                unsigned m = __ballot_sync(0xffffffffu, hit);
                if (m) { found = base + __ffs(m) - 1; break; }
            }
            if (found < 0) break;
            float a = sA[found];
            float acc = (float)(sS[found] + Ccorr);
            float ak1 = 1.f - acc;
            float ak2 = a - ak1;
            if (lane == 0) {
                s_fire_t[ntok] = found;
                s_ak1[ntok] = ak1;
                s_ak2[ntok] = ak2;
            }
            Ccorr += (double)a - 1.0;
            ntok++;
            pos = found + 1;
        }
        __syncwarp();
        if (lane == 0) { s_ntok = ntok; g_nf[b] = ntok; }
        for (int i = lane; i < ntok; i += 32) {
            g_fire_t[b * MAXTOK + i] = s_fire_t[i];
            g_fak1[b * MAXTOK + i] = s_ak1[i];
            g_fak2[b * MAXTOK + i] = s_ak2[i];
        }
    }
    __syncthreads();

    // --- step 5: fill aws sparse entries (memset provided the zeros) ---
    int ntok = s_ntok;
    float* awb = aws + (size_t)b * (L + 1) * T;
    for (int t = tid; t < el; t += 1024) {
        int lo = 0, hi = ntok;
        while (lo < hi) {
            int m = (lo + hi) >> 1;
            if (s_fire_t[m] < t) lo = m + 1; else hi = m;
        }
        int row = lo;
        if (row < ntok && s_fire_t[row] == t) {
            awb[row * T + t] = s_ak1[row];
            awb[(row + 1) * T + t] = s_ak2[row];
        } else if (row < yl) {
            awb[row * T + t] = sA[t];
        }
    }
}

// ---------------- kernel 4: per-token 4-phase reduction -> fired -------------
// block (512 threads) per (token, batch): thread (ph, d) accumulates the
// d-th float4 over t = t0+ph, t0+ph+4, ...; boundary coefs folded into w(t);
// 4-way smem tree-sum at the end. 4x the loads in flight vs 1-phase.
__global__ void __launch_bounds__(512)
k_fired(const float* __restrict__ eouts, float* __restrict__ fired, int L) {
    int b = blockIdx.y;
    int n = blockIdx.x;
    if (n >= g_nf[b]) return;
    int e = g_fire_t[b * MAXTOK + n];
    float c1 = g_fak1[b * MAXTOK + n];
    int s; float c0;
    if (n == 0) { s = -1; c0 = 0.f; }
    else { s = g_fire_t[b * MAXTOK + n - 1]; c0 = g_fak2[b * MAXTOK + n - 1]; }

    int d  = threadIdx.x & 127;   // float4 slice of D
    int ph = threadIdx.x >> 7;    // 0..3 time phase

    const float* an = g_anorm + b * T;
    const float4* eb = (const float4*)(eouts + (size_t)b * T * D);

    int t0 = (s >= 0) ? s : 0;
    float4 acc = make_float4(0.f, 0.f, 0.f, 0.f);
    #pragma unroll 4
    for (int t = t0 + ph; t <= e; t += 4) {
        float w = (t == e) ? c1 : ((t == s) ? c0 : an[t]);
        float4 v = eb[(size_t)t * 128 + d];
        acc.x += w * v.x; acc.y += w * v.y;
        acc.z += w * v.z; acc.w += w * v.w;
    }

    __shared__ float4 sAcc[512];
    sAcc[threadIdx.x] = acc;
    __syncthreads();
    if (ph == 0) {
        float4 a1 = sAcc[128 + d], a2 = sAcc[256 + d], a3 = sAcc[384 + d];
        acc.x += a1.x + a2.x + a3.x;
        acc.y += a1.y + a2.y + a3.y;
        acc.z += a1.z + a2.z + a3.z;
        acc.w += a1.w + a2.w + a3.w;
        ((float4*)(fired + ((size_t)b * L + n) * D))[d] = acc;
    }
}

// ---------------- launch ------------------------------------------------------
extern "C" void kernel_launch(void* const* d_in, const int* in_sizes, int n_in,
                              void* d_out, int out_size) {
    const float* eouts  = (const float*)d_in[0];
    const float* conv_w = (const float*)d_in[1];
    const float* conv_b = (const float*)d_in[2];
    const float* proj_w = (const float*)d_in[3];
    const float* proj_b = (const float*)d_in[4];
    const int*   elens  = (const int*)d_in[5];
    const int*   ylens  = (const int*)d_in[6];

    // out = concat(fired[B,L,D], alpha[B,T], aws[B,1,L+1,T])
    int L = (out_size - 2 * B * T) / (B * D + B * T);

    float* out   = (float*)d_out;
    float* fired = out;
    float* alpha = out + (size_t)B * L * D;
    float* aws   = alpha + (size_t)B * T;

    cudaMemsetAsync(d_out, 0, (size_t)out_size * sizeof(float));

    k_weff<<<(KW * D + 1 + 7) / 8, 256>>>(conv_w, conv_b, proj_w, proj_b);
    k_logit<<<dim3(T / TILE, B), 128>>>(eouts);
    k_alpha_scan<<<B, 1024>>>(alpha, aws, elens, ylens, L);
    k_fired<<<dim3(L, B), 512>>>(eouts, fired, L);
}